// round 2
// baseline (speedup 1.0000x reference)
#include <cuda_runtime.h>

#define N      64
#define L      8192
#define BATCH  2048
#define Q      64
#define CHUNKS (L / Q)      // 128
#define ZDIM   128          // N + Q
#define RTILE  16
#define TB     128

// Fused per-chunk transition matrix P (ZDIM x ZDIM), row-major:
//   rows 0..63   = state features x[n], rows 64..127 = chunk inputs u[i]
//   cols 0..63   = chunk outputs y[tau], cols 64..127 = new state x'[n']
//   P[n][tau]        = (C Ab^{tau+1})[n]                 (Wout^T)
//   P[64+i][tau]     = K[tau-i] (i<=tau) + D (i==tau)    (lower-tri Toeplitz)
//   P[n][64+n']      = (Ab^64)[n'][n]                    (M^T)
//   P[64+i][64+n']   = (Ab^{63-i} Bb)[n']                (Win)
__device__ float  d_P[ZDIM * ZDIM];
__device__ double d_Abd[N * N];
__device__ double d_Bbd[N];
__device__ double d_Cd[N];
__device__ double d_Dd;

// ---------------------------------------------------------------------------
// Setup phase 1 (1 block, 256 threads, fp64):
// Gauss-Jordan inverse of (I - (s/2)A), then Ab = BL(I + (s/2)A), Bb = s BL B.
// ---------------------------------------------------------------------------
__global__ void ssm_setup1(const float* __restrict__ A,
                           const float* __restrict__ B,
                           const float* __restrict__ C,
                           const float* __restrict__ D,
                           const float* __restrict__ log_step) {
    extern __shared__ double G[];          // 64 x 128
    __shared__ double fac[N];

    const int tid = threadIdx.x;
    const int nt  = blockDim.x;
    const double s = exp((double)log_step[0]);

    // G = [ I - (s/2)A | I ]
    for (int idx = tid; idx < 64 * 128; idx += nt) {
        int i = idx >> 7, j = idx & 127;
        double v;
        if (j < 64) v = (i == j ? 1.0 : 0.0) - 0.5 * s * (double)A[i * 64 + j];
        else        v = ((j - 64) == i) ? 1.0 : 0.0;
        G[idx] = v;
    }
    __syncthreads();

    // Gauss-Jordan, no pivoting (strong diagonal dominance: ||(s/2)A|| << 1).
    // BL = inv(I - (s/2)A) lands in G[:, 64:128].
    for (int p = 0; p < 64; ++p) {
        double pivinv = 1.0 / G[p * 128 + p];
        __syncthreads();
        for (int j = tid; j < 128; j += nt) G[p * 128 + j] *= pivinv;
        for (int i = tid; i < 64;  i += nt) fac[i] = G[i * 128 + p];
        __syncthreads();
        for (int idx = tid; idx < 64 * 128; idx += nt) {
            int i = idx >> 7, j = idx & 127;
            if (i != p) G[idx] -= fac[i] * G[p * 128 + j];
        }
        __syncthreads();
    }

    // Overwrite left half with RHS = I + (s/2)A (no longer needed: it's I now)
    for (int idx = tid; idx < 64 * 64; idx += nt) {
        int i = idx >> 6, j = idx & 63;
        G[i * 128 + j] = (i == j ? 1.0 : 0.0) + 0.5 * s * (double)A[i * 64 + j];
    }
    __syncthreads();

    // Ab = BL @ RHS
    for (int idx = tid; idx < 64 * 64; idx += nt) {
        int i = idx >> 6, j = idx & 63;
        double acc = 0.0;
        for (int m = 0; m < 64; ++m)
            acc += G[i * 128 + 64 + m] * G[m * 128 + j];
        d_Abd[idx] = acc;
    }
    // Bb = s * BL @ B; stash C, D
    if (tid < 64) {
        double acc = 0.0;
        for (int m = 0; m < 64; ++m) acc += G[tid * 128 + 64 + m] * (double)B[m];
        d_Bbd[tid] = s * acc;
        d_Cd[tid]  = (double)C[tid];
    }
    if (tid == 0) d_Dd = (double)D[0];
}

// ---------------------------------------------------------------------------
// Setup phase 2 (192 blocks x 64 threads, fp64): independent matvec chains.
//   role 0 (blocks   0- 63): row n' of M = e_{n'}^T Ab^64  -> P[n][64+n']
//   role 1 (blocks  64-127): C Ab^{t+1}                    -> P[n][t]
//   role 2 (blocks 128-191): c_p = Ab^p Bb -> Win row 64+(63-p); K[p] -> Toeplitz diag
// ---------------------------------------------------------------------------
__global__ void ssm_setup2() {
    __shared__ double Abs[N * N];
    __shared__ double v[N], vn[N], red[N];

    const int tid  = threadIdx.x;      // 64 threads
    const int role = blockIdx.x >> 6;
    const int idx  = blockIdx.x & 63;

    for (int i = tid; i < N * N; i += 64) Abs[i] = d_Abd[i];

    int steps;
    if (role == 0)      { v[tid] = (tid == idx) ? 1.0 : 0.0; steps = 64; }
    else if (role == 1) { v[tid] = d_Cd[tid];                steps = idx + 1; }
    else                { v[tid] = d_Bbd[tid];               steps = idx; }
    __syncthreads();

    if (role <= 1) {
        // row-chain: v' = v^T Ab
        for (int t = 0; t < steps; ++t) {
            double acc = 0.0;
            #pragma unroll 8
            for (int m = 0; m < 64; ++m) acc += v[m] * Abs[m * 64 + tid];
            __syncthreads();
            v[tid] = acc;
            __syncthreads();
        }
        if (role == 0) d_P[tid * ZDIM + 64 + idx] = (float)v[tid];   // M^T col
        else           d_P[tid * ZDIM + idx]      = (float)v[tid];   // Wout^T col
    } else {
        // col-chain: v' = Ab v
        for (int t = 0; t < steps; ++t) {
            double acc = 0.0;
            #pragma unroll 8
            for (int m = 0; m < 64; ++m) acc += Abs[tid * 64 + m] * v[m];
            __syncthreads();
            v[tid] = acc;
            __syncthreads();
        }
        // Win row: P[64 + (63-idx)][64 + n'] = c_idx[n']
        d_P[(64 + (63 - idx)) * ZDIM + 64 + tid] = (float)v[tid];
        // K[idx] = C . c_idx  (tree reduce in shared)
        red[tid] = d_Cd[tid] * v[tid];
        __syncthreads();
        for (int off = 32; off > 0; off >>= 1) {
            if (tid < off) red[tid] += red[tid + off];
            __syncthreads();
        }
        double kv = red[0];
        if (idx == 0) kv += d_Dd;   // diagonal gets +D
        // Toeplitz diagonal offset idx: P[64+i][i+idx] = K[idx], i = 0..63-idx
        if (tid + idx < 64)
            d_P[(64 + tid) * ZDIM + (tid + idx)] = (float)kv;
    }
}

// ---------------------------------------------------------------------------
// Main kernel: 128 CTAs x 128 threads.  Each CTA owns RTILE=16 batch rows and
// walks 128 chunks sequentially:  [Y | Xnew] = [X | U] @ P  (16x128x128 GEMM).
// Thread tiling: 4 rows x 4 cols per thread (2048 outputs / 128 threads).
// ---------------------------------------------------------------------------
__global__ void __launch_bounds__(TB, 1)
ssm_main(const float* __restrict__ u, float* __restrict__ y) {
    extern __shared__ float sm[];
    float* Ps = sm;                 // 128 x 128
    float* Z  = sm + ZDIM * ZDIM;   // RTILE x 128, row-major: [X | U]

    const int tid = threadIdx.x;
    const long rowBase = (long)blockIdx.x * RTILE;

    for (int i = tid; i < ZDIM * ZDIM; i += TB) Ps[i] = d_P[i];
    for (int i = tid; i < RTILE * ZDIM; i += TB) Z[i] = 0.f;   // X = 0

    const int cg = tid & 31;   // column group: cols c0..c0+3 over all 128
    const int rg = tid >> 5;   // row group:    rows r0..r0+3 over 16
    const int c0 = cg * 4, r0 = rg * 4;

    // U-staging map: index -> (row = idx>>4, float4 slot = idx&15)
    const int ia = tid, ib = tid + TB;
    const int ra = ia >> 4, qa = ia & 15;
    const int rb = ib >> 4, qb = ib & 15;

    // prefetch chunk 0
    float4 pre0 = reinterpret_cast<const float4*>(u + (rowBase + ra) * L)[qa];
    float4 pre1 = reinterpret_cast<const float4*>(u + (rowBase + rb) * L)[qb];

    for (int j = 0; j < CHUNKS; ++j) {
        // stage prefetched U into Z[:, 64:128]
        *reinterpret_cast<float4*>(&Z[ra * ZDIM + 64 + qa * 4]) = pre0;
        *reinterpret_cast<float4*>(&Z[rb * ZDIM + 64 + qb * 4]) = pre1;
        __syncthreads();

        // issue next chunk's global loads (overlaps with compute)
        if (j + 1 < CHUNKS) {
            pre0 = reinterpret_cast<const float4*>(u + (rowBase + ra) * L + (j + 1) * Q)[qa];
            pre1 = reinterpret_cast<const float4*>(u + (rowBase + rb) * L + (j + 1) * Q)[qb];
        }

        float4 a0 = make_float4(0.f, 0.f, 0.f, 0.f);
        float4 a1 = a0, a2 = a0, a3 = a0;

        #pragma unroll 16
        for (int k = 0; k < ZDIM; ++k) {
            float4 p = *reinterpret_cast<const float4*>(&Ps[k * ZDIM + c0]);
            float z0 = Z[(r0 + 0) * ZDIM + k];
            float z1 = Z[(r0 + 1) * ZDIM + k];
            float z2 = Z[(r0 + 2) * ZDIM + k];
            float z3 = Z[(r0 + 3) * ZDIM + k];
            a0.x += z0 * p.x; a0.y += z0 * p.y; a0.z += z0 * p.z; a0.w += z0 * p.w;
            a1.x += z1 * p.x; a1.y += z1 * p.y; a1.z += z1 * p.z; a1.w += z1 * p.w;
            a2.x += z2 * p.x; a2.y += z2 * p.y; a2.z += z2 * p.z; a2.w += z2 * p.w;
            a3.x += z3 * p.x; a3.y += z3 * p.y; a3.z += z3 * p.z; a3.w += z3 * p.w;
        }
        __syncthreads();

        if (c0 < Q) {
            // Y outputs -> global (float4, coalesced)
            float* yb = y + (rowBase + r0) * L + j * Q + c0;
            *reinterpret_cast<float4*>(yb + 0 * L) = a0;
            *reinterpret_cast<float4*>(yb + 1 * L) = a1;
            *reinterpret_cast<float4*>(yb + 2 * L) = a2;
            *reinterpret_cast<float4*>(yb + 3 * L) = a3;
        } else {
            // new state -> Z[:, 0:64]
            int cc = c0 - 64;
            float* z0p = &Z[(r0 + 0) * ZDIM + cc];
            float* z1p = &Z[(r0 + 1) * ZDIM + cc];
            float* z2p = &Z[(r0 + 2) * ZDIM + cc];
            float* z3p = &Z[(r0 + 3) * ZDIM + cc];
            z0p[0] = a0.x; z0p[1] = a0.y; z0p[2] = a0.z; z0p[3] = a0.w;
            z1p[0] = a1.x; z1p[1] = a1.y; z1p[2] = a1.z; z1p[3] = a1.w;
            z2p[0] = a2.x; z2p[1] = a2.y; z2p[2] = a2.z; z2p[3] = a2.w;
            z3p[0] = a3.x; z3p[1] = a3.y; z3p[2] = a3.z; z3p[3] = a3.w;
        }
        // no extra sync needed: U-store + X-store touch disjoint Z regions;
        // next iteration's __syncthreads orders them before the compute.
    }
}

extern "C" void kernel_launch(void* const* d_in, const int* in_sizes, int n_in,
                              void* d_out, int out_size) {
    const float* u  = (const float*)d_in[0];
    const float* A  = (const float*)d_in[1];
    const float* B  = (const float*)d_in[2];
    const float* C  = (const float*)d_in[3];
    const float* D  = (const float*)d_in[4];
    const float* ls = (const float*)d_in[5];
    float* y = (float*)d_out;

    const int smemSetup1 = 64 * 128 * 8;                          // 64 KB (double)
    const int smemMain   = (ZDIM * ZDIM + RTILE * ZDIM) * 4;      // 72 KB

    cudaFuncSetAttribute(ssm_setup1, cudaFuncAttributeMaxDynamicSharedMemorySize, smemSetup1);
    cudaFuncSetAttribute(ssm_main,   cudaFuncAttributeMaxDynamicSharedMemorySize, smemMain);

    ssm_setup1<<<1, 256, smemSetup1>>>(A, B, C, D, ls);
    ssm_setup2<<<192, 64>>>();
    ssm_main<<<BATCH / RTILE, TB, smemMain>>>(u, y);
}

// round 3
// speedup vs baseline: 1.3324x; 1.3324x over previous
#include <cuda_runtime.h>

#define N      64
#define L      8192
#define BATCH  2048
#define Q      64
#define CHUNKS 128
#define ZDIM   128
#define RTILE  16
#define TB     256
#define ZSTRIDE 17   // doubles per feature (16 rows + 1 pad, kills bank conflicts)

// Fused per-chunk transition matrix P (ZDIM x ZDIM), row-major:
//   P[n][t]        = (C Ab^{t+1})[n]                  (Wout^T)
//   P[64+i][t]     = K[t-i] (i<=t) + D (i==t)         (lower-tri Toeplitz)
//   P[n][64+n']    = (Ab^64)[n'][n]                   (M^T)
//   P[64+i][64+n'] = (Ab^{63-i} Bb)[n']               (Win)
__device__ float  d_P[ZDIM * ZDIM];

// fp64 setup workspace
__device__ double d_T[N * N];      // I - (s/2)A
__device__ double d_R[N * N];      // I + (s/2)A
__device__ double d_X[N * N];      // inverse iterate
__device__ double d_X2[N * N];
__device__ double d_E[N * N];
__device__ double d_Ab[N * N];
__device__ double d_SA[N * N];     // squaring ping-pong
__device__ double d_SB[N * N];     // final: Ab^64
__device__ double d_Bb[N];
__device__ double d_Bvec[N];
__device__ double d_Cv[N];
__device__ double d_Dv;
__device__ double d_step;
__device__ double d_Rm[65][N];     // r_t = C Ab^t
__device__ double d_Cm[64][N];     // c_p = Ab^p Bb

// ---------------------------------------------------------------------------
// Setup: fp32 Gauss-Jordan (fast pipe) for approximate inverse; stash fp64 T,R.
// ---------------------------------------------------------------------------
__global__ void ssm_gj(const float* __restrict__ A, const float* __restrict__ B,
                       const float* __restrict__ C, const float* __restrict__ Dp,
                       const float* __restrict__ ls) {
    __shared__ float G[64 * 128];
    __shared__ float fac[64];
    const int tid = threadIdx.x, nt = 256;
    const double sd = exp((double)ls[0]);
    const float  s  = (float)sd;

    for (int idx = tid; idx < 64 * 64; idx += nt) {
        int i = idx >> 6, j = idx & 63;
        double a = (double)A[idx];
        d_T[idx] = (i == j ? 1.0 : 0.0) - 0.5 * sd * a;
        d_R[idx] = (i == j ? 1.0 : 0.0) + 0.5 * sd * a;
    }
    for (int idx = tid; idx < 64 * 128; idx += nt) {
        int i = idx >> 7, j = idx & 127;
        G[idx] = (j < 64) ? ((i == j ? 1.f : 0.f) - 0.5f * s * A[i * 64 + j])
                          : (((j - 64) == i) ? 1.f : 0.f);
    }
    if (tid < 64) { d_Cv[tid] = (double)C[tid]; d_Bvec[tid] = (double)B[tid]; }
    if (tid == 0) { d_Dv = (double)Dp[0]; d_step = sd; }
    __syncthreads();

    for (int p = 0; p < 64; ++p) {
        float pivinv = 1.f / G[p * 128 + p];
        __syncthreads();
        for (int j = tid; j < 128; j += nt) G[p * 128 + j] *= pivinv;
        for (int i = tid; i < 64;  i += nt) fac[i] = G[i * 128 + p];
        __syncthreads();
        for (int idx = tid; idx < 64 * 128; idx += nt) {
            int i = idx >> 7, j = idx & 127;
            if (i != p) G[idx] -= fac[i] * G[p * 128 + j];
        }
        __syncthreads();
    }
    for (int idx = tid; idx < 64 * 64; idx += nt) {
        int i = idx >> 6, j = idx & 63;
        d_X[idx] = (double)G[i * 128 + 64 + j];
    }
}

// ---------------------------------------------------------------------------
// Generic fp64 64x64 matmul, one row per block, 64 threads.
//   mode 0: Out = A@B   mode 1: Out = I - A@B   mode 2: Out = A + A@B
// ---------------------------------------------------------------------------
__global__ void mm64(const double* __restrict__ A, const double* __restrict__ B,
                     double* __restrict__ Out, int mode) {
    __shared__ double ar[64];
    const int i = blockIdx.x, j = threadIdx.x;
    ar[j] = A[i * 64 + j];
    __syncthreads();
    double acc = 0.0;
    #pragma unroll 8
    for (int m = 0; m < 64; ++m) acc += ar[m] * B[m * 64 + j];
    if (mode == 1)      acc = ((i == j) ? 1.0 : 0.0) - acc;
    else if (mode == 2) acc += ar[j];
    Out[i * 64 + j] = acc;
}

// ---------------------------------------------------------------------------
// Ab = X@R (blocks 0..63, also seeds nothing else), Bb = s*X@B (block 64),
// seeds Rm[0]=C, Cm[0]=Bb.
// ---------------------------------------------------------------------------
__global__ void ssm_abbb() {
    const int b = blockIdx.x, i = threadIdx.x;
    if (b < 64) {
        __shared__ double xr[64];
        xr[i] = d_X[b * 64 + i];
        __syncthreads();
        double acc = 0.0;
        #pragma unroll 8
        for (int m = 0; m < 64; ++m) acc += xr[m] * d_R[m * 64 + i];
        d_Ab[b * 64 + i] = acc;
    } else {
        double acc = 0.0;
        for (int m = 0; m < 64; ++m) acc += d_X[i * 64 + m] * d_Bvec[m];
        double bb = d_step * acc;
        d_Bb[i] = bb;
        d_Cm[0][i] = bb;
        d_Rm[0][i] = d_Cv[i];
    }
}

// ---------------------------------------------------------------------------
// Doubling level j: extends Rm/Cm by 2^j entries using S=Ab^{2^j}, and squares
// S into Snext. Blocks: [0,nr) r-chain, [nr,nr+twoJ) c-chain, rest squaring.
// ---------------------------------------------------------------------------
__global__ void ssm_level(int twoJ, int nr, const double* __restrict__ S,
                          double* __restrict__ Snext) {
    __shared__ double v[64];
    const int b = blockIdx.x, i = threadIdx.x;
    if (b < nr) {
        int t = b;
        v[i] = d_Rm[t][i];
        __syncthreads();
        double acc = 0.0;
        #pragma unroll 8
        for (int m = 0; m < 64; ++m) acc += v[m] * S[m * 64 + i];
        d_Rm[t + twoJ][i] = acc;
    } else if (b < nr + twoJ) {
        int p = b - nr;
        v[i] = d_Cm[p][i];
        __syncthreads();
        double acc = 0.0;
        #pragma unroll 8
        for (int m = 0; m < 64; ++m) acc += S[i * 64 + m] * v[m];
        d_Cm[p + twoJ][i] = acc;
    } else {
        int r = b - nr - twoJ;
        v[i] = S[r * 64 + i];
        __syncthreads();
        double acc = 0.0;
        #pragma unroll 8
        for (int m = 0; m < 64; ++m) acc += v[m] * S[m * 64 + i];
        Snext[r * 64 + i] = acc;
    }
}

// ---------------------------------------------------------------------------
// Finalize: K dots, r_64 = C@M, fill fp32 P.
// ---------------------------------------------------------------------------
__global__ void ssm_fin() {
    __shared__ double Kk[64];
    __shared__ double r64[64];
    const int tid = threadIdx.x;      // 256
    const double* M = d_SB;           // Ab^64
    if (tid < 64) {
        double acc = 0.0;
        for (int m = 0; m < 64; ++m) acc += d_Cv[m] * d_Cm[tid][m];
        if (tid == 0) acc += d_Dv;
        Kk[tid] = acc;
    } else if (tid < 128) {
        int n = tid - 64;
        double acc = 0.0;
        for (int m = 0; m < 64; ++m) acc += d_Cv[m] * M[m * 64 + n];
        r64[n] = acc;
    }
    __syncthreads();
    for (int idx = tid; idx < ZDIM * ZDIM; idx += 256) {
        int i = idx >> 7, c = idx & 127;
        double v;
        if (i < 64) {
            if (c < 64) v = (c < 63) ? d_Rm[c + 1][i] : r64[i];
            else        v = M[(c - 64) * 64 + i];
        } else {
            int ii = i - 64;
            if (c < 64) v = (ii <= c) ? Kk[c - ii] : 0.0;
            else        v = d_Cm[63 - ii][c - 64];
        }
        d_P[idx] = (float)v;
    }
}

// ---------------------------------------------------------------------------
// Packed f32x2 helpers
// ---------------------------------------------------------------------------
__device__ __forceinline__ void ffma2(unsigned long long& acc,
                                      unsigned long long a, unsigned long long b) {
    asm("fma.rn.f32x2 %0, %1, %2, %0;" : "+l"(acc) : "l"(a), "l"(b));
}
__device__ __forceinline__ unsigned long long dup2(float v) {
    unsigned long long r;
    asm("mov.b64 %0, {%1, %1};" : "=l"(r) : "f"(v));
    return r;
}
__device__ __forceinline__ float2 unpk(unsigned long long p) {
    float2 f;
    asm("mov.b64 {%0, %1}, %2;" : "=f"(f.x), "=f"(f.y) : "l"(p));
    return f;
}

// ---------------------------------------------------------------------------
// Main: 128 CTAs x 256 threads (8 warps). Warp w owns batch rows 2w, 2w+1 of
// its CTA's 16-row tile — Z is warp-local (no block barriers in the loop).
// Per chunk: [Y | Xnew] = [X | U] @ P via packed fma.rn.f32x2.
// Z stored transposed + value-duplicated: Zd[k][r] = {z, z} so the broadcast
// operand needs no packing in the inner loop.
// ---------------------------------------------------------------------------
__global__ void __launch_bounds__(TB, 1)
ssm_main(const float* __restrict__ u, float* __restrict__ y) {
    extern __shared__ float sm[];
    float* Ps = sm;                                                   // 128x128
    unsigned long long* Zd =
        reinterpret_cast<unsigned long long*>(sm + ZDIM * ZDIM);      // [128][ZSTRIDE]

    const int tid = threadIdx.x;
    const long rowBase = (long)blockIdx.x * RTILE;

    for (int i = tid; i < ZDIM * ZDIM; i += TB) Ps[i] = d_P[i];
    for (int i = tid; i < 64 * RTILE; i += TB) {                      // X = 0
        int k = i >> 4, r = i & 15;
        Zd[k * ZSTRIDE + r] = 0ULL;
    }
    __syncthreads();

    const int cg = tid & 31, rg = tid >> 5;
    const int c0 = cg * 4, r0 = rg * 2;
    const int rs = tid >> 4, tau4 = (tid & 15) * 4;   // staging map (warp-local)

    const float* urow = u + (rowBase + rs) * L + tau4;
    unsigned long long* zstage = &Zd[(64 + tau4) * ZSTRIDE + rs];

    float4 pre = *reinterpret_cast<const float4*>(urow);

    const bool isY = (c0 < Q);
    float* ybase = y + (rowBase + r0) * L + c0;
    const int cc = c0 - 64;
    const unsigned long long* zp = Zd + r0;
    const float* pp = Ps + c0;

    for (int j = 0; j < CHUNKS; ++j) {
        // stage duplicated U (warp-local rows)
        zstage[0 * ZSTRIDE] = dup2(pre.x);
        zstage[1 * ZSTRIDE] = dup2(pre.y);
        zstage[2 * ZSTRIDE] = dup2(pre.z);
        zstage[3 * ZSTRIDE] = dup2(pre.w);
        __syncwarp();

        if (j + 1 < CHUNKS)
            pre = *reinterpret_cast<const float4*>(urow + (j + 1) * Q);

        unsigned long long aA0 = 0, aB0 = 0, aA1 = 0, aB1 = 0;
        #pragma unroll 8
        for (int k = 0; k < ZDIM; ++k) {
            ulonglong2 p2 = *reinterpret_cast<const ulonglong2*>(pp + k * ZDIM);
            unsigned long long z0 = zp[k * ZSTRIDE];
            unsigned long long z1 = zp[k * ZSTRIDE + 1];
            ffma2(aA0, p2.x, z0); ffma2(aB0, p2.y, z0);
            ffma2(aA1, p2.x, z1); ffma2(aB1, p2.y, z1);
        }
        __syncwarp();

        if (isY) {
            *reinterpret_cast<ulonglong2*>(ybase + (long)j * Q)     = make_ulonglong2(aA0, aB0);
            *reinterpret_cast<ulonglong2*>(ybase + (long)j * Q + L) = make_ulonglong2(aA1, aB1);
        } else {
            float2 f;
            f = unpk(aA0); Zd[(cc + 0) * ZSTRIDE + r0]     = dup2(f.x);
                           Zd[(cc + 1) * ZSTRIDE + r0]     = dup2(f.y);
            f = unpk(aB0); Zd[(cc + 2) * ZSTRIDE + r0]     = dup2(f.x);
                           Zd[(cc + 3) * ZSTRIDE + r0]     = dup2(f.y);
            f = unpk(aA1); Zd[(cc + 0) * ZSTRIDE + r0 + 1] = dup2(f.x);
                           Zd[(cc + 1) * ZSTRIDE + r0 + 1] = dup2(f.y);
            f = unpk(aB1); Zd[(cc + 2) * ZSTRIDE + r0 + 1] = dup2(f.x);
                           Zd[(cc + 3) * ZSTRIDE + r0 + 1] = dup2(f.y);
        }
    }
}

extern "C" void kernel_launch(void* const* d_in, const int* in_sizes, int n_in,
                              void* d_out, int out_size) {
    const float* u  = (const float*)d_in[0];
    const float* A  = (const float*)d_in[1];
    const float* B  = (const float*)d_in[2];
    const float* C  = (const float*)d_in[3];
    const float* D  = (const float*)d_in[4];
    const float* ls = (const float*)d_in[5];
    float* y = (float*)d_out;

    double *pT, *pX, *pX2, *pE, *pAb, *pSA, *pSB;
    cudaGetSymbolAddress((void**)&pT,  d_T);
    cudaGetSymbolAddress((void**)&pX,  d_X);
    cudaGetSymbolAddress((void**)&pX2, d_X2);
    cudaGetSymbolAddress((void**)&pE,  d_E);
    cudaGetSymbolAddress((void**)&pAb, d_Ab);
    cudaGetSymbolAddress((void**)&pSA, d_SA);
    cudaGetSymbolAddress((void**)&pSB, d_SB);

    const int smemMain = ZDIM * ZDIM * 4 + ZDIM * ZSTRIDE * 8;   // 82944 B
    cudaFuncSetAttribute(ssm_main, cudaFuncAttributeMaxDynamicSharedMemorySize, smemMain);

    ssm_gj<<<1, 256>>>(A, B, C, D, ls);
    // Newton refinement (fp64), 2 iterations: X <- X + X(I - T X)
    mm64<<<64, 64>>>(pT,  pX,  pE,  1);
    mm64<<<64, 64>>>(pX,  pE,  pX2, 2);
    mm64<<<64, 64>>>(pT,  pX2, pE,  1);
    mm64<<<64, 64>>>(pX2, pE,  pX,  2);
    ssm_abbb<<<65, 64>>>();

    // Doubling levels: chains + squaring fused.  S ping-pong: Ab->SA->SB->...
    const double* Sptr[6]  = {pAb, pSA, pSB, pSA, pSB, pSA};
    double*       Snext[6] = {pSA, pSB, pSA, pSB, pSA, pSB};   // level 5 -> SB = Ab^64
    for (int j = 0; j < 6; ++j) {
        int twoJ = 1 << j;
        int nr = twoJ;                       // r-chain blocks (t in [0, 2^j))
        ssm_level<<<nr + twoJ + 64, 64>>>(twoJ, nr, Sptr[j], Snext[j]);
    }
    ssm_fin<<<1, 256>>>();

    ssm_main<<<BATCH / RTILE, TB, smemMain>>>(u, y);
}